// round 1
// baseline (speedup 1.0000x reference)
#include <cuda_runtime.h>
#include <math.h>

#define B_     64
#define NSIDE  40
#define NPTS   1600
#define S_     512
#define C1_    20
#define W_     128
#define K4BLKS 256   // s-chunks of 2 in K4

// ---------------- scratch (device globals; no runtime allocation) ----------------
__device__ float g_filt1[S_ * C1_ * NPTS];   // [s][c][n]
__device__ float g_z1   [S_ * C1_ * B_];     // [(s*20+c)*64 + b]  (silu'd, /N applied)
__device__ float g_h2   [S_ * W_];           // [s][128]
__device__ float g_filt2[S_ * C1_ * W_];     // [s*2560 + c*128 + w]
__device__ float g_z2p  [K4BLKS * B_ * W_];  // partial sums for stage D

// FirstLayer MLP weights in constant memory -> LDCU uniform-port loads
__constant__ float c_flw1[400];
__constant__ float c_flb1[20];
__constant__ float c_flw2[400];
__constant__ float c_flb2[20];
__constant__ float c_flw3[400];
__constant__ float c_flb3[20];

__device__ __forceinline__ float silu_f(float x) { return x / (1.0f + __expf(-x)); }

// ---------------- K1: filt1[s,c,n] = MLP(embed(projective coords)) ----------------
__global__ __launch_bounds__(256) void k1_filt1(const float* __restrict__ v_last)
{
    int s = blockIdx.y;
    int n = blockIdx.x * blockDim.x + threadIdx.x;
    if (n >= NPTS) return;

    float v[8];
#pragma unroll
    for (int i = 0; i < 8; i++) v[i] = 0.1f * v_last[s * 8 + i];

    int ic = n / NSIDE, jc = n % NSIDE;
    float x = -1.0f + (2.0f / 39.0f) * (float)ic;
    float y = -1.0f + (2.0f / 39.0f) * (float)jc;

    // H = I + pert (row-major, pert[2][2]=0)
    float y0 = (1.0f + v[0]) * x + v[1] * y + v[2];
    float y1 = v[3] * x + (1.0f + v[4]) * y + v[5];
    float y2 = v[6] * x + v[7] * y + 1.0f;
    float t0 = y0 / y2;
    float t1 = y1 / y2;

    // sinusoidal embed: [sin(t0*f), cos(t0*f), sin(t1*f), cos(t1*f)], f=1,2,4,8,16
    float e[20];
#pragma unroll
    for (int k = 0; k < 5; k++) {
        float f = (float)(1 << k);
        float s0, c0, s1, c1;
        __sincosf(t0 * f, &s0, &c0);
        __sincosf(t1 * f, &s1, &c1);
        e[k] = s0; e[5 + k] = c0; e[10 + k] = s1; e[15 + k] = c1;
    }

    float h1[20];
#pragma unroll
    for (int o = 0; o < 20; o++) {
        float a = c_flb1[o];
#pragma unroll
        for (int i = 0; i < 20; i++) a += e[i] * c_flw1[i * 20 + o];
        h1[o] = silu_f(a);
    }
    float h2[20];
#pragma unroll
    for (int o = 0; o < 20; o++) {
        float a = c_flb2[o];
#pragma unroll
        for (int i = 0; i < 20; i++) a += h1[i] * c_flw2[i * 20 + o];
        h2[o] = silu_f(a);
    }
#pragma unroll
    for (int o = 0; o < 20; o++) {
        float a = c_flb3[o];
#pragma unroll
        for (int i = 0; i < 20; i++) a += h2[i] * c_flw3[i * 20 + o];
        g_filt1[(s * C1_ + o) * NPTS + n] = a;   // coalesced over n
    }
}

// ---------------- K2: z1[s,c,b] = silu( (1/N) * data[b,:] . filt1[s,:,c] ) --------
// grid = 128 blocks (4 s each), 256 threads. Register tile: 4b x 5c per thread.
#define TN 64
__global__ __launch_bounds__(256) void k2_z1(const float* __restrict__ data)
{
    __shared__ float dt[TN * 65];          // [nl][b], stride 65 (conflict-free)
    __shared__ float ft[4 * 20 * 65];      // [sl][c][nl], stride 65

    int s0  = blockIdx.x * 4;
    int tid = threadIdx.x;
    int sl  = tid >> 6;
    int r   = tid & 63;
    int bq  = r & 15;       // b = bq + 16*i
    int cg  = r >> 4;       // c = cg + 4*j

    float acc[4][5];
#pragma unroll
    for (int i = 0; i < 4; i++)
#pragma unroll
        for (int j = 0; j < 5; j++) acc[i][j] = 0.0f;

    for (int n0 = 0; n0 < NPTS; n0 += TN) {
        __syncthreads();
        // data tile: coalesced global reads, conflict-free smem stores
        for (int i = tid; i < TN * B_; i += 256) {
            int bb = i >> 6, nl = i & 63;
            dt[nl * 65 + bb] = data[bb * NPTS + n0 + nl];
        }
        // filter tile
        for (int i = tid; i < 4 * 20 * TN; i += 256) {
            int ss = i / 1280;
            int rem = i - ss * 1280;
            int c = rem >> 6, nl = rem & 63;
            ft[(ss * 20 + c) * 65 + nl] = g_filt1[((s0 + ss) * C1_ + c) * NPTS + n0 + nl];
        }
        __syncthreads();

        for (int nl = 0; nl < TN; nl++) {
            float d[4];
#pragma unroll
            for (int i = 0; i < 4; i++) d[i] = dt[nl * 65 + bq + 16 * i];
#pragma unroll
            for (int j = 0; j < 5; j++) {
                float f = ft[(sl * 20 + cg + 4 * j) * 65 + nl];
#pragma unroll
                for (int i = 0; i < 4; i++) acc[i][j] += d[i] * f;
            }
        }
    }

    int s = s0 + sl;
#pragma unroll
    for (int i = 0; i < 4; i++) {
        int b = bq + 16 * i;
#pragma unroll
        for (int j = 0; j < 5; j++) {
            int c = cg + 4 * j;
            g_z1[(s * C1_ + c) * B_ + b] = silu_f(acc[i][j] * (1.0f / (float)NPTS));
        }
    }
}

// ---------------- K3a: h2[s,:] = silu(embed(v0[s]) @ s_w1 + s_b1) -----------------
__global__ __launch_bounds__(128) void k3a_h2(const float* __restrict__ v0,
                                              const float* __restrict__ s_w1,
                                              const float* __restrict__ s_b1)
{
    __shared__ float e[80];
    int s = blockIdx.x, tid = threadIdx.x;
    if (tid < 80) {
        int d = tid / 10, kk = tid % 10;
        float v = v0[s * 8 + d];
        float f = (float)(1 << (kk % 5));
        e[tid] = (kk < 5) ? __sinf(v * f) : __cosf(v * f);
    }
    __syncthreads();
    float a = s_b1[tid];
#pragma unroll 8
    for (int k = 0; k < 80; k++) a += e[k] * s_w1[k * W_ + tid];
    g_h2[s * W_ + tid] = silu_f(a);
}

// ---------------- K3b: filt2[s, o] = h2[s,:] @ s_w2[:, o] + s_b2[o] ---------------
// grid (32 s-chunks x 20 o-chunks), 256 threads, tile 16s x 128o, reg tile 2s x 4o
__global__ __launch_bounds__(256) void k3b_filt2(const float* __restrict__ s_w2,
                                                 const float* __restrict__ s_b2)
{
    __shared__ float h2s[16 * 128];
    __shared__ float wt[32 * 128];
    int s0 = blockIdx.x * 16;
    int o0 = blockIdx.y * 128;
    int tid = threadIdx.x;

    for (int i = tid; i < 16 * 128; i += 256) h2s[i] = g_h2[s0 * W_ + i];

    int sq = tid >> 5;   // s = sq, sq+8
    int ow = tid & 31;   // o = ow + 32*m
    float acc[2][4];
#pragma unroll
    for (int p = 0; p < 2; p++)
#pragma unroll
        for (int m = 0; m < 4; m++) acc[p][m] = 0.0f;

    for (int k0 = 0; k0 < 128; k0 += 32) {
        __syncthreads();
        for (int i = tid; i < 32 * 128; i += 256) {
            int kk = i >> 7, o = i & 127;
            wt[kk * 128 + o] = s_w2[(k0 + kk) * 2560 + o0 + o];
        }
        __syncthreads();
        for (int kk = 0; kk < 32; kk++) {
            float h0 = h2s[sq * 128 + k0 + kk];
            float h1 = h2s[(sq + 8) * 128 + k0 + kk];
#pragma unroll
            for (int m = 0; m < 4; m++) {
                float w = wt[kk * 128 + ow + 32 * m];
                acc[0][m] += h0 * w;
                acc[1][m] += h1 * w;
            }
        }
    }
#pragma unroll
    for (int p = 0; p < 2; p++) {
        int s = s0 + sq + 8 * p;
#pragma unroll
        for (int m = 0; m < 4; m++) {
            int o = o0 + ow + 32 * m;
            g_filt2[s * 2560 + o] = acc[p][m] + s_b2[o];
        }
    }
}

// ---------------- K4: z2p[chunk,b,w] = sum over 2 s of z1[s,c,b]*filt2[s,c,w] -----
// grid 256 blocks (2 s each), 256 threads, reg tile 4b x 8w
__global__ __launch_bounds__(256) void k4_contract()
{
    __shared__ float zt[40 * 64];    // [(sl*20+c)][b]
    __shared__ float ft[40 * 128];   // [(sl*20+c)][w]
    int chunk = blockIdx.x;
    int s0 = chunk * 2;
    int tid = threadIdx.x;

    for (int i = tid; i < 40 * 64; i += 256)  zt[i] = g_z1[s0 * C1_ * B_ + i];
    for (int i = tid; i < 40 * 128; i += 256) ft[i] = g_filt2[s0 * 2560 + i];
    __syncthreads();

    int wq = tid & 15;   // w = wq + 16*k
    int bq = tid >> 4;   // b = bq + 16*i
    float acc[4][8];
#pragma unroll
    for (int i = 0; i < 4; i++)
#pragma unroll
        for (int k = 0; k < 8; k++) acc[i][k] = 0.0f;

    for (int sc = 0; sc < 40; sc++) {
        float z[4];
#pragma unroll
        for (int i = 0; i < 4; i++) z[i] = zt[sc * 64 + bq + 16 * i];
#pragma unroll
        for (int k = 0; k < 8; k++) {
            float f = ft[sc * 128 + wq + 16 * k];
#pragma unroll
            for (int i = 0; i < 4; i++) acc[i][k] += z[i] * f;
        }
    }
#pragma unroll
    for (int i = 0; i < 4; i++)
#pragma unroll
        for (int k = 0; k < 8; k++)
            g_z2p[chunk * (B_ * W_) + (bq + 16 * i) * W_ + wq + 16 * k] = acc[i][k];
}

// ---------------- K5: reduce partials, residual MLP, pool -------------------------
__global__ __launch_bounds__(128) void k5_head(const float* __restrict__ fc1_w,
                                               const float* __restrict__ fc1_b,
                                               const float* __restrict__ fc2_w,
                                               const float* __restrict__ fc2_b,
                                               const float* __restrict__ pool_w,
                                               const float* __restrict__ pool_b,
                                               float* __restrict__ out)
{
    __shared__ float zs[128], r1[128], r2[128];
    int b = blockIdx.x, w = threadIdx.x;

    float a = 0.0f;
#pragma unroll 8
    for (int p = 0; p < K4BLKS; p++) a += g_z2p[p * (B_ * W_) + b * W_ + w];
    a *= (1.0f / (float)S_);
    zs[w] = a;
    __syncthreads();

    float u = fc1_b[w];
#pragma unroll 8
    for (int k = 0; k < 128; k++) u += zs[k] * fc1_w[k * W_ + w];
    r1[w] = silu_f(u) + zs[w];
    __syncthreads();

    u = fc2_b[w];
#pragma unroll 8
    for (int k = 0; k < 128; k++) u += r1[k] * fc2_w[k * W_ + w];
    r2[w] = silu_f(u) + r1[w];
    __syncthreads();

    if (w < 10) {
        float o = pool_b[w];
        for (int k = 0; k < 128; k++) o += r2[k] * pool_w[k * 10 + w];
        out[b * 10 + w] = o;
    }
}

// ---------------- host launcher ---------------------------------------------------
extern "C" void kernel_launch(void* const* d_in, const int* in_sizes, int n_in,
                              void* d_out, int out_size)
{
    const float* data   = (const float*)d_in[0];
    const float* v0     = (const float*)d_in[1];
    const float* v_last = (const float*)d_in[2];
    const float* s_w1   = (const float*)d_in[9];
    const float* s_b1   = (const float*)d_in[10];
    const float* s_w2   = (const float*)d_in[11];
    const float* s_b2   = (const float*)d_in[12];
    const float* fc1_w  = (const float*)d_in[13];
    const float* fc1_b  = (const float*)d_in[14];
    const float* fc2_w  = (const float*)d_in[15];
    const float* fc2_b  = (const float*)d_in[16];
    const float* pool_w = (const float*)d_in[17];
    const float* pool_b = (const float*)d_in[18];

    // FirstLayer MLP weights -> constant memory (D2D async, graph-capturable)
    cudaMemcpyToSymbolAsync(c_flw1, d_in[3], 400 * sizeof(float), 0, cudaMemcpyDeviceToDevice, 0);
    cudaMemcpyToSymbolAsync(c_flb1, d_in[4],  20 * sizeof(float), 0, cudaMemcpyDeviceToDevice, 0);
    cudaMemcpyToSymbolAsync(c_flw2, d_in[5], 400 * sizeof(float), 0, cudaMemcpyDeviceToDevice, 0);
    cudaMemcpyToSymbolAsync(c_flb2, d_in[6],  20 * sizeof(float), 0, cudaMemcpyDeviceToDevice, 0);
    cudaMemcpyToSymbolAsync(c_flw3, d_in[7], 400 * sizeof(float), 0, cudaMemcpyDeviceToDevice, 0);
    cudaMemcpyToSymbolAsync(c_flb3, d_in[8],  20 * sizeof(float), 0, cudaMemcpyDeviceToDevice, 0);

    k1_filt1<<<dim3(7, S_), 256>>>(v_last);
    k2_z1<<<128, 256>>>(data);
    k3a_h2<<<S_, 128>>>(v0, s_w1, s_b1);
    k3b_filt2<<<dim3(32, 20), 256>>>(s_w2, s_b2);
    k4_contract<<<K4BLKS, 256>>>();
    k5_head<<<B_, 128>>>(fc1_w, fc1_b, fc2_w, fc2_b, pool_w, pool_b, (float*)d_out);
}

// round 2
// speedup vs baseline: 1.1892x; 1.1892x over previous
#include <cuda_runtime.h>
#include <math.h>

#define B_     64
#define NSIDE  40
#define NPTS   1600
#define S_     512
#define C1_    20
#define W_     128
#define K4BLKS 256   // s-chunks of 2 in K4

// ---------------- scratch (device globals; no runtime allocation) ----------------
__device__ float g_filt1[S_ * C1_ * NPTS];   // [s][c][n]
__device__ float g_z1   [S_ * C1_ * B_];     // [(s*20+c)*64 + b]  (silu'd, /N applied)
__device__ float g_h2   [S_ * W_];           // [s][128]
__device__ float g_filt2[S_ * C1_ * W_];     // [s*2560 + c*128 + w]
__device__ float g_z2p  [K4BLKS * B_ * W_];  // partial sums for stage D

__device__ __forceinline__ float silu_f(float x) { return x / (1.0f + __expf(-x)); }

// ---------------- K1: filt1[s,c,n] = MLP(embed(projective coords)) ----------------
// GEMM-style: 128 threads, 256-point tile, weights in smem, reg tile 8p x 5o.
// Avoids the Blackwell LDC half-rate-port trap (no cbank ALU operands on sm_103a).
__global__ __launch_bounds__(128) void k1_filt1(
    const float* __restrict__ v_last,
    const float* __restrict__ fw1, const float* __restrict__ fb1,
    const float* __restrict__ fw2, const float* __restrict__ fb2,
    const float* __restrict__ fw3, const float* __restrict__ fb3)
{
    __shared__ float sw1[400], sw2[400], sw3[400];
    __shared__ float sb1[20],  sb2[20],  sb3[20];
    __shared__ float bufA[256 * 21], bufB[256 * 21];   // [p][feat], stride 21 (odd -> bank clean)

    int s   = blockIdx.y;
    int n0  = blockIdx.x * 256;
    int tid = threadIdx.x;

    for (int i = tid; i < 400; i += 128) { sw1[i] = fw1[i]; sw2[i] = fw2[i]; sw3[i] = fw3[i]; }
    if (tid < 20) { sb1[tid] = fb1[tid]; sb2[tid] = fb2[tid]; sb3[tid] = fb3[tid]; }

    float v[8];
#pragma unroll
    for (int i = 0; i < 8; i++) v[i] = 0.1f * __ldg(&v_last[s * 8 + i]);

    // ---- embed phase: 2 points per thread ----
#pragma unroll
    for (int q = 0; q < 2; q++) {
        int p = tid + q * 128;
        int n = n0 + p;
        float x = 0.0f, y = 0.0f;
        if (n < NPTS) {
            int ic = n / NSIDE, jc = n % NSIDE;
            x = -1.0f + (2.0f / 39.0f) * (float)ic;
            y = -1.0f + (2.0f / 39.0f) * (float)jc;
        }
        float y0 = (1.0f + v[0]) * x + v[1] * y + v[2];
        float y1 = v[3] * x + (1.0f + v[4]) * y + v[5];
        float y2 = v[6] * x + v[7] * y + 1.0f;
        float inv = 1.0f / y2;
        float t0 = y0 * inv, t1 = y1 * inv;
#pragma unroll
        for (int k = 0; k < 5; k++) {
            float f = (float)(1 << k);
            float s0, c0, s1, c1;
            __sincosf(t0 * f, &s0, &c0);
            __sincosf(t1 * f, &s1, &c1);
            bufA[p * 21 + k]      = s0;
            bufA[p * 21 + 5 + k]  = c0;
            bufA[p * 21 + 10 + k] = s1;
            bufA[p * 21 + 15 + k] = c1;
        }
    }
    __syncthreads();

    int pq = tid & 31;        // lane -> point group (p = pq + 32*ip)
    int ob = (tid >> 5) * 5;  // warp -> 5 consecutive outputs

    // ---- layer 1: bufA -> bufB ----
    {
        float acc[8][5];
#pragma unroll
        for (int ip = 0; ip < 8; ip++)
#pragma unroll
            for (int j = 0; j < 5; j++) acc[ip][j] = sb1[ob + j];
#pragma unroll 4
        for (int i = 0; i < 20; i++) {
            float w5[5];
#pragma unroll
            for (int j = 0; j < 5; j++) w5[j] = sw1[i * 20 + ob + j];   // warp broadcast
#pragma unroll
            for (int ip = 0; ip < 8; ip++) {
                float e = bufA[(pq + 32 * ip) * 21 + i];
#pragma unroll
                for (int j = 0; j < 5; j++) acc[ip][j] += e * w5[j];
            }
        }
#pragma unroll
        for (int ip = 0; ip < 8; ip++)
#pragma unroll
            for (int j = 0; j < 5; j++)
                bufB[(pq + 32 * ip) * 21 + ob + j] = silu_f(acc[ip][j]);
    }
    __syncthreads();

    // ---- layer 2: bufB -> bufA ----
    {
        float acc[8][5];
#pragma unroll
        for (int ip = 0; ip < 8; ip++)
#pragma unroll
            for (int j = 0; j < 5; j++) acc[ip][j] = sb2[ob + j];
#pragma unroll 4
        for (int i = 0; i < 20; i++) {
            float w5[5];
#pragma unroll
            for (int j = 0; j < 5; j++) w5[j] = sw2[i * 20 + ob + j];
#pragma unroll
            for (int ip = 0; ip < 8; ip++) {
                float e = bufB[(pq + 32 * ip) * 21 + i];
#pragma unroll
                for (int j = 0; j < 5; j++) acc[ip][j] += e * w5[j];
            }
        }
#pragma unroll
        for (int ip = 0; ip < 8; ip++)
#pragma unroll
            for (int j = 0; j < 5; j++)
                bufA[(pq + 32 * ip) * 21 + ob + j] = silu_f(acc[ip][j]);
    }
    __syncthreads();

    // ---- layer 3: bufA -> global (coalesced over n) ----
    {
        float acc[8][5];
#pragma unroll
        for (int ip = 0; ip < 8; ip++)
#pragma unroll
            for (int j = 0; j < 5; j++) acc[ip][j] = sb3[ob + j];
#pragma unroll 4
        for (int i = 0; i < 20; i++) {
            float w5[5];
#pragma unroll
            for (int j = 0; j < 5; j++) w5[j] = sw3[i * 20 + ob + j];
#pragma unroll
            for (int ip = 0; ip < 8; ip++) {
                float e = bufA[(pq + 32 * ip) * 21 + i];
#pragma unroll
                for (int j = 0; j < 5; j++) acc[ip][j] += e * w5[j];
            }
        }
#pragma unroll
        for (int ip = 0; ip < 8; ip++) {
            int n = n0 + pq + 32 * ip;
            if (n < NPTS) {
#pragma unroll
                for (int j = 0; j < 5; j++)
                    g_filt1[(s * C1_ + ob + j) * NPTS + n] = acc[ip][j];
            }
        }
    }
}

// ---------------- K2: z1[s,c,b] = silu( (1/N) * data[b,:] . filt1[s,:,c] ) --------
// grid = 128 blocks (4 s each), 256 threads. Register tile: 4b x 5c per thread.
#define TN 64
__global__ __launch_bounds__(256) void k2_z1(const float* __restrict__ data)
{
    __shared__ float dt[TN * 65];          // [nl][b], stride 65 (conflict-free)
    __shared__ float ft[4 * 20 * 65];      // [sl][c][nl], stride 65

    int s0  = blockIdx.x * 4;
    int tid = threadIdx.x;
    int sl  = tid >> 6;
    int r   = tid & 63;
    int bq  = r & 15;       // b = bq + 16*i
    int cg  = r >> 4;       // c = cg + 4*j

    float acc[4][5];
#pragma unroll
    for (int i = 0; i < 4; i++)
#pragma unroll
        for (int j = 0; j < 5; j++) acc[i][j] = 0.0f;

    for (int n0 = 0; n0 < NPTS; n0 += TN) {
        __syncthreads();
        for (int i = tid; i < TN * B_; i += 256) {
            int bb = i >> 6, nl = i & 63;
            dt[nl * 65 + bb] = data[bb * NPTS + n0 + nl];
        }
        for (int i = tid; i < 4 * 20 * TN; i += 256) {
            int ss = i / 1280;
            int rem = i - ss * 1280;
            int c = rem >> 6, nl = rem & 63;
            ft[(ss * 20 + c) * 65 + nl] = g_filt1[((s0 + ss) * C1_ + c) * NPTS + n0 + nl];
        }
        __syncthreads();

        for (int nl = 0; nl < TN; nl++) {
            float d[4];
#pragma unroll
            for (int i = 0; i < 4; i++) d[i] = dt[nl * 65 + bq + 16 * i];
#pragma unroll
            for (int j = 0; j < 5; j++) {
                float f = ft[(sl * 20 + cg + 4 * j) * 65 + nl];
#pragma unroll
                for (int i = 0; i < 4; i++) acc[i][j] += d[i] * f;
            }
        }
    }

    int s = s0 + sl;
#pragma unroll
    for (int i = 0; i < 4; i++) {
        int b = bq + 16 * i;
#pragma unroll
        for (int j = 0; j < 5; j++) {
            int c = cg + 4 * j;
            g_z1[(s * C1_ + c) * B_ + b] = silu_f(acc[i][j] * (1.0f / (float)NPTS));
        }
    }
}

// ---------------- K3a: h2[s,:] = silu(embed(v0[s]) @ s_w1 + s_b1) -----------------
__global__ __launch_bounds__(128) void k3a_h2(const float* __restrict__ v0,
                                              const float* __restrict__ s_w1,
                                              const float* __restrict__ s_b1)
{
    __shared__ float e[80];
    int s = blockIdx.x, tid = threadIdx.x;
    if (tid < 80) {
        int d = tid / 10, kk = tid % 10;
        float v = v0[s * 8 + d];
        float f = (float)(1 << (kk % 5));
        e[tid] = (kk < 5) ? __sinf(v * f) : __cosf(v * f);
    }
    __syncthreads();
    float a = s_b1[tid];
#pragma unroll 8
    for (int k = 0; k < 80; k++) a += e[k] * s_w1[k * W_ + tid];
    g_h2[s * W_ + tid] = silu_f(a);
}

// ---------------- K3b: filt2[s,o] = h2[s,:] @ s_w2[:,o] + s_b2[o] -----------------
// tile 32s x 256o, grid (16, 10), 256 threads, reg tile 4s x 8o -> 12 LDS / 32 FMA
__global__ __launch_bounds__(256) void k3b_filt2(const float* __restrict__ s_w2,
                                                 const float* __restrict__ s_b2)
{
    __shared__ float h2s[32 * 128];   // 16 KB
    __shared__ float wt[32 * 256];    // 32 KB
    int s0  = blockIdx.x * 32;
    int o0  = blockIdx.y * 256;
    int tid = threadIdx.x;

    for (int i = tid; i < 32 * 128; i += 256) h2s[i] = g_h2[s0 * W_ + i];

    int sq = tid >> 5;   // s = s0 + sq + 8*p
    int ow = tid & 31;   // o = o0 + ow + 32*m

    float acc[4][8];
#pragma unroll
    for (int m = 0; m < 8; m++) {
        float b = s_b2[o0 + ow + 32 * m];
#pragma unroll
        for (int p = 0; p < 4; p++) acc[p][m] = b;
    }

    for (int k0 = 0; k0 < 128; k0 += 32) {
        __syncthreads();
        for (int i = tid; i < 32 * 256; i += 256) {
            int kk = i >> 8, o = i & 255;
            wt[i] = s_w2[(k0 + kk) * 2560 + o0 + o];
        }
        __syncthreads();
        for (int kk = 0; kk < 32; kk++) {
            float h[4];
#pragma unroll
            for (int p = 0; p < 4; p++) h[p] = h2s[(sq + 8 * p) * 128 + k0 + kk];  // broadcast
#pragma unroll
            for (int m = 0; m < 8; m++) {
                float w = wt[kk * 256 + ow + 32 * m];
#pragma unroll
                for (int p = 0; p < 4; p++) acc[p][m] += h[p] * w;
            }
        }
    }
#pragma unroll
    for (int p = 0; p < 4; p++)
#pragma unroll
        for (int m = 0; m < 8; m++)
            g_filt2[(s0 + sq + 8 * p) * 2560 + o0 + ow + 32 * m] = acc[p][m];
}

// ---------------- K4: z2p[chunk,b,w] = sum over 2 s of z1[s,c,b]*filt2[s,c,w] -----
__global__ __launch_bounds__(256) void k4_contract()
{
    __shared__ float zt[40 * 64];    // [(sl*20+c)][b]
    __shared__ float ft[40 * 128];   // [(sl*20+c)][w]
    int chunk = blockIdx.x;
    int s0 = chunk * 2;
    int tid = threadIdx.x;

    for (int i = tid; i < 40 * 64; i += 256)  zt[i] = g_z1[s0 * C1_ * B_ + i];
    for (int i = tid; i < 40 * 128; i += 256) ft[i] = g_filt2[s0 * 2560 + i];
    __syncthreads();

    int wq = tid & 15;   // w = wq + 16*k
    int bq = tid >> 4;   // b = bq + 16*i
    float acc[4][8];
#pragma unroll
    for (int i = 0; i < 4; i++)
#pragma unroll
        for (int k = 0; k < 8; k++) acc[i][k] = 0.0f;

    for (int sc = 0; sc < 40; sc++) {
        float z[4];
#pragma unroll
        for (int i = 0; i < 4; i++) z[i] = zt[sc * 64 + bq + 16 * i];
#pragma unroll
        for (int k = 0; k < 8; k++) {
            float f = ft[sc * 128 + wq + 16 * k];
#pragma unroll
            for (int i = 0; i < 4; i++) acc[i][k] += z[i] * f;
        }
    }
#pragma unroll
    for (int i = 0; i < 4; i++)
#pragma unroll
        for (int k = 0; k < 8; k++)
            g_z2p[chunk * (B_ * W_) + (bq + 16 * i) * W_ + wq + 16 * k] = acc[i][k];
}

// ---------------- K5: reduce partials, residual MLP, pool -------------------------
__global__ __launch_bounds__(128) void k5_head(const float* __restrict__ fc1_w,
                                               const float* __restrict__ fc1_b,
                                               const float* __restrict__ fc2_w,
                                               const float* __restrict__ fc2_b,
                                               const float* __restrict__ pool_w,
                                               const float* __restrict__ pool_b,
                                               float* __restrict__ out)
{
    __shared__ float zs[128], r1[128], r2[128];
    int b = blockIdx.x, w = threadIdx.x;

    float a = 0.0f;
#pragma unroll 8
    for (int p = 0; p < K4BLKS; p++) a += g_z2p[p * (B_ * W_) + b * W_ + w];
    a *= (1.0f / (float)S_);
    zs[w] = a;
    __syncthreads();

    float u = fc1_b[w];
#pragma unroll 8
    for (int k = 0; k < 128; k++) u += zs[k] * fc1_w[k * W_ + w];
    r1[w] = silu_f(u) + zs[w];
    __syncthreads();

    u = fc2_b[w];
#pragma unroll 8
    for (int k = 0; k < 128; k++) u += r1[k] * fc2_w[k * W_ + w];
    r2[w] = silu_f(u) + r1[w];
    __syncthreads();

    if (w < 10) {
        float o = pool_b[w];
        for (int k = 0; k < 128; k++) o += r2[k] * pool_w[k * 10 + w];
        out[b * 10 + w] = o;
    }
}

// ---------------- host launcher ---------------------------------------------------
extern "C" void kernel_launch(void* const* d_in, const int* in_sizes, int n_in,
                              void* d_out, int out_size)
{
    const float* data   = (const float*)d_in[0];
    const float* v0     = (const float*)d_in[1];
    const float* v_last = (const float*)d_in[2];
    const float* fl_w1  = (const float*)d_in[3];
    const float* fl_b1  = (const float*)d_in[4];
    const float* fl_w2  = (const float*)d_in[5];
    const float* fl_b2  = (const float*)d_in[6];
    const float* fl_w3  = (const float*)d_in[7];
    const float* fl_b3  = (const float*)d_in[8];
    const float* s_w1   = (const float*)d_in[9];
    const float* s_b1   = (const float*)d_in[10];
    const float* s_w2   = (const float*)d_in[11];
    const float* s_b2   = (const float*)d_in[12];
    const float* fc1_w  = (const float*)d_in[13];
    const float* fc1_b  = (const float*)d_in[14];
    const float* fc2_w  = (const float*)d_in[15];
    const float* fc2_b  = (const float*)d_in[16];
    const float* pool_w = (const float*)d_in[17];
    const float* pool_b = (const float*)d_in[18];

    k1_filt1<<<dim3(7, S_), 128>>>(v_last, fl_w1, fl_b1, fl_w2, fl_b2, fl_w3, fl_b3);
    k2_z1<<<128, 256>>>(data);
    k3a_h2<<<S_, 128>>>(v0, s_w1, s_b1);
    k3b_filt2<<<dim3(16, 10), 256>>>(s_w2, s_b2);
    k4_contract<<<K4BLKS, 256>>>();
    k5_head<<<B_, 128>>>(fc1_w, fc1_b, fc2_w, fc2_b, pool_w, pool_b, (float*)d_out);
}

// round 3
// speedup vs baseline: 1.6839x; 1.4160x over previous
#include <cuda_runtime.h>
#include <math.h>

#define B_     64
#define NSIDE  40
#define NPTS   1600
#define S_     512
#define C1_    20
#define W_     128
#define SCN    10240                 // S_*C1_ : GEMM "M" dim of stage B
#define KSPLIT 4
#define ZPSZ   (SCN * B_)            // one split's partial plane
#define K4BLKS 256                   // s-chunks of 2 in K4

typedef unsigned long long u64;

// ---------------- scratch (device globals; no runtime allocation) ----------------
__device__ __align__(16) float g_filt1[S_ * C1_ * NPTS];   // [sc][n]
__device__ __align__(16) float g_z1p [KSPLIT * ZPSZ];      // [split][sc*64+b] partials
__device__ __align__(16) float g_h2  [S_ * W_];            // [s][128]
__device__ __align__(16) float g_filt2[S_ * C1_ * W_];     // [s*2560 + c*128 + w]
__device__ __align__(16) float g_z2p [K4BLKS * B_ * W_];   // partials for stage D

// ---------------- f32x2 helpers (Blackwell packed fp32 FMA) -----------------------
__device__ __forceinline__ u64 pk2(float lo, float hi) {
    u64 r; asm("mov.b64 %0, {%1, %2};" : "=l"(r) : "f"(lo), "f"(hi)); return r;
}
__device__ __forceinline__ void upk2(u64 v, float& lo, float& hi) {
    asm("mov.b64 {%0, %1}, %2;" : "=f"(lo), "=f"(hi) : "l"(v));
}
__device__ __forceinline__ void fma2p(u64& d, u64 a, u64 b) {
    asm("fma.rn.f32x2 %0, %1, %2, %0;" : "+l"(d) : "l"(a), "l"(b));
}

__device__ __forceinline__ float silu_f(float x) { return x / (1.0f + __expf(-x)); }
// 1-MUFU silu via HW tanh: x*sigmoid(x) = 0.5x + 0.5x*tanh(x/2)
__device__ __forceinline__ float silu_t(float x) {
    float t; asm("tanh.approx.f32 %0, %1;" : "=f"(t) : "f"(0.5f * x));
    return 0.5f * x * (1.0f + t);
}

// ---------------- K1: filt1[sc][n] = MLP(embed(projective coords)) ----------------
// 128 threads, 256-pt tile. f32x2 over output-pairs (weights LDS.64 broadcast),
// scalar e dup-packed. Tanh silu, double-angle embed.
#define BP 264   // buf row stride [feat][point]

__device__ __forceinline__ void k1_layer(const float* in, float* out,
                                         const float* w, const float* bias,
                                         int og, int pl)
{
    int ob = og * 10;
    u64 acc[4][5];
#pragma unroll
    for (int ip = 0; ip < 4; ip++)
#pragma unroll
        for (int j = 0; j < 5; j++) acc[ip][j] = pk2(bias[ob + 2*j], bias[ob + 2*j + 1]);
#pragma unroll 4
    for (int i = 0; i < 20; i++) {
        u64 wv[5];
#pragma unroll
        for (int j = 0; j < 5; j++)
            wv[j] = *(const u64*)&w[i * 20 + ob + 2 * j];   // LDS.64 broadcast
#pragma unroll
        for (int ip = 0; ip < 4; ip++) {
            float e = in[i * BP + pl + 64 * ip];
            u64 ed = pk2(e, e);
#pragma unroll
            for (int j = 0; j < 5; j++) fma2p(acc[ip][j], ed, wv[j]);
        }
    }
#pragma unroll
    for (int ip = 0; ip < 4; ip++)
#pragma unroll
        for (int j = 0; j < 5; j++) {
            float a0, a1; upk2(acc[ip][j], a0, a1);
            out[(ob + 2*j)     * BP + pl + 64 * ip] = silu_t(a0);
            out[(ob + 2*j + 1) * BP + pl + 64 * ip] = silu_t(a1);
        }
}

__global__ __launch_bounds__(128) void k1_filt1(
    const float* __restrict__ v_last,
    const float* __restrict__ fw1, const float* __restrict__ fb1,
    const float* __restrict__ fw2, const float* __restrict__ fb2,
    const float* __restrict__ fw3, const float* __restrict__ fb3)
{
    __shared__ __align__(16) float sw1[400], sw2[400], sw3[400];
    __shared__ float sb1[20], sb2[20], sb3[20];
    __shared__ __align__(16) float bufA[20 * BP], bufB[20 * BP];

    int s   = blockIdx.y;
    int n0  = blockIdx.x * 256;
    int tid = threadIdx.x;

    for (int i = tid; i < 400; i += 128) { sw1[i] = fw1[i]; sw2[i] = fw2[i]; sw3[i] = fw3[i]; }
    if (tid < 20) { sb1[tid] = fb1[tid]; sb2[tid] = fb2[tid]; sb3[tid] = fb3[tid]; }

    float v[8];
#pragma unroll
    for (int i = 0; i < 8; i++) v[i] = 0.1f * __ldg(&v_last[s * 8 + i]);

    // ---- embed: 2 points per thread, double-angle recurrence ----
#pragma unroll
    for (int q = 0; q < 2; q++) {
        int p = tid + q * 128;
        int n = n0 + p;
        int ic = n / NSIDE, jc = n - ic * NSIDE;
        float x = -1.0f + (2.0f / 39.0f) * (float)ic;
        float y = -1.0f + (2.0f / 39.0f) * (float)jc;
        float y0 = (1.0f + v[0]) * x + v[1] * y + v[2];
        float y1 = v[3] * x + (1.0f + v[4]) * y + v[5];
        float y2 = v[6] * x + v[7] * y + 1.0f;
        float inv = __frcp_rn(y2);
        float t0 = y0 * inv, t1 = y1 * inv;

        float sa, ca; __sincosf(t0, &sa, &ca);
        bufA[0 * BP + p] = sa; bufA[5 * BP + p] = ca;
#pragma unroll
        for (int k = 1; k < 5; k++) {
            float s2 = 2.0f * sa * ca;
            float c2 = 2.0f * ca * ca - 1.0f;
            bufA[k * BP + p] = s2; bufA[(5 + k) * BP + p] = c2;
            sa = s2; ca = c2;
        }
        __sincosf(t1, &sa, &ca);
        bufA[10 * BP + p] = sa; bufA[15 * BP + p] = ca;
#pragma unroll
        for (int k = 1; k < 5; k++) {
            float s2 = 2.0f * sa * ca;
            float c2 = 2.0f * ca * ca - 1.0f;
            bufA[(10 + k) * BP + p] = s2; bufA[(15 + k) * BP + p] = c2;
            sa = s2; ca = c2;
        }
    }
    __syncthreads();

    int og = tid >> 6;    // output half: o base = og*10
    int pl = tid & 63;    // point lane: p = pl + 64*ip

    k1_layer(bufA, bufB, sw1, sb1, og, pl);
    __syncthreads();
    k1_layer(bufB, bufA, sw2, sb2, og, pl);
    __syncthreads();

    // ---- layer 3 (no activation) -> global [sc][n] ----
    {
        int ob = og * 10;
        u64 acc[4][5];
#pragma unroll
        for (int ip = 0; ip < 4; ip++)
#pragma unroll
            for (int j = 0; j < 5; j++) acc[ip][j] = pk2(sb3[ob + 2*j], sb3[ob + 2*j + 1]);
#pragma unroll 4
        for (int i = 0; i < 20; i++) {
            u64 wv[5];
#pragma unroll
            for (int j = 0; j < 5; j++) wv[j] = *(const u64*)&sw3[i * 20 + ob + 2 * j];
#pragma unroll
            for (int ip = 0; ip < 4; ip++) {
                float e = bufA[i * BP + pl + 64 * ip];
                u64 ed = pk2(e, e);
#pragma unroll
                for (int j = 0; j < 5; j++) fma2p(acc[ip][j], ed, wv[j]);
            }
        }
#pragma unroll
        for (int ip = 0; ip < 4; ip++) {
            int n = n0 + pl + 64 * ip;
            if (n < NPTS) {
#pragma unroll
                for (int j = 0; j < 5; j++) {
                    float a0, a1; upk2(acc[ip][j], a0, a1);
                    g_filt1[(s * C1_ + ob + 2*j)     * NPTS + n] = a0;
                    g_filt1[(s * C1_ + ob + 2*j + 1) * NPTS + n] = a1;
                }
            }
        }
    }
}

// ---------------- K2: z1p[split][sc*64+b] = filt1[sc,:] . data[b,:] over n-range --
// Single GEMM M=10240, N=64, K=1600 split 4x400; f32x2 over b-pairs.
// 128 threads, sc-tile 128, chunk kc=40. 8sc x 8b per thread.
__global__ __launch_bounds__(128) void k2_z1(const float* __restrict__ data)
{
    __shared__ __align__(16) float dt[40 * 66];    // [k][b]
    __shared__ float ft[40 * 129];                 // [k][sc_local]

    int sc0   = blockIdx.x * 128;
    int split = blockIdx.y;
    int tid   = threadIdx.x;
    int tc    = tid & 7;     // b-pair base 2*tc (+16*jp)
    int sr    = tid >> 3;    // sc local = sr + 16*iq

    u64 acc[8][4];
#pragma unroll
    for (int iq = 0; iq < 8; iq++)
#pragma unroll
        for (int jp = 0; jp < 4; jp++) acc[iq][jp] = 0ull;

    for (int ch = 0; ch < 10; ch++) {
        int base = split * 400 + ch * 40;
        __syncthreads();
        for (int i = tid; i < 64 * 40; i += 128) {
            int b = i / 40, k = i - b * 40;
            dt[k * 66 + b] = data[b * NPTS + base + k];
        }
        for (int i = tid; i < 128 * 40; i += 128) {
            int r = i / 40, k = i - r * 40;
            ft[k * 129 + r] = g_filt1[(sc0 + r) * NPTS + base + k];
        }
        __syncthreads();

#pragma unroll 2
        for (int k = 0; k < 40; k++) {
            u64 fd[8];
#pragma unroll
            for (int iq = 0; iq < 8; iq++) {
                float f = ft[k * 129 + sr + 16 * iq];
                fd[iq] = pk2(f, f);
            }
            u64 dd[4];
#pragma unroll
            for (int jp = 0; jp < 4; jp++)
                dd[jp] = *(const u64*)&dt[k * 66 + 2 * tc + 16 * jp];
#pragma unroll
            for (int iq = 0; iq < 8; iq++)
#pragma unroll
                for (int jp = 0; jp < 4; jp++) fma2p(acc[iq][jp], fd[iq], dd[jp]);
        }
    }

#pragma unroll
    for (int iq = 0; iq < 8; iq++)
#pragma unroll
        for (int jp = 0; jp < 4; jp++)
            *(u64*)&g_z1p[split * ZPSZ + (sc0 + sr + 16 * iq) * B_ + 2 * tc + 16 * jp]
                = acc[iq][jp];
}

// ---------------- K3a: h2[s,:] = silu(embed(v0[s]) @ s_w1 + s_b1) -----------------
__global__ __launch_bounds__(128) void k3a_h2(const float* __restrict__ v0,
                                              const float* __restrict__ s_w1,
                                              const float* __restrict__ s_b1)
{
    __shared__ float e[80];
    int s = blockIdx.x, tid = threadIdx.x;
    if (tid < 80) {
        int d = tid / 10, kk = tid % 10;
        float v = v0[s * 8 + d];
        float f = (float)(1 << (kk % 5));
        e[tid] = (kk < 5) ? __sinf(v * f) : __cosf(v * f);
    }
    __syncthreads();
    float a = s_b1[tid];
#pragma unroll 8
    for (int k = 0; k < 80; k++) a += e[k] * s_w1[k * W_ + tid];
    g_h2[s * W_ + tid] = silu_f(a);
}

// ---------------- K3b: filt2[s,o] = h2[s,:] @ s_w2[:,o] + s_b2[o] -----------------
// tile 16s x 128o, grid (32,20), 128 threads, reg tile 4s x 4o (8 LDS / 16 FMA)
__global__ __launch_bounds__(128) void k3b_filt2(const float* __restrict__ s_w2,
                                                 const float* __restrict__ s_b2)
{
    __shared__ float h2s[16 * 128];   // 8 KB
    __shared__ float wt[32 * 128];    // 16 KB
    int s0  = blockIdx.x * 16;
    int o0  = blockIdx.y * 128;
    int tid = threadIdx.x;
    int ow  = tid & 31;   // o = o0 + ow + 32*m
    int sq  = tid >> 5;   // s = s0 + sq*4 + p

    for (int i = tid; i < 16 * 128; i += 128) h2s[i] = g_h2[s0 * W_ + i];

    float acc[4][4];
#pragma unroll
    for (int m = 0; m < 4; m++) {
        float b = s_b2[o0 + ow + 32 * m];
#pragma unroll
        for (int p = 0; p < 4; p++) acc[p][m] = b;
    }

    for (int k0 = 0; k0 < 128; k0 += 32) {
        __syncthreads();
        for (int i = tid; i < 32 * 128; i += 128) {
            int kk = i >> 7, o = i & 127;
            wt[i] = s_w2[(k0 + kk) * 2560 + o0 + o];
        }
        __syncthreads();
#pragma unroll 4
        for (int kk = 0; kk < 32; kk++) {
            float h[4];
#pragma unroll
            for (int p = 0; p < 4; p++) h[p] = h2s[(sq * 4 + p) * 128 + k0 + kk];
#pragma unroll
            for (int m = 0; m < 4; m++) {
                float w = wt[kk * 128 + ow + 32 * m];
#pragma unroll
                for (int p = 0; p < 4; p++) acc[p][m] += h[p] * w;
            }
        }
    }
#pragma unroll
    for (int p = 0; p < 4; p++)
#pragma unroll
        for (int m = 0; m < 4; m++)
            g_filt2[(s0 + sq * 4 + p) * 2560 + o0 + ow + 32 * m] = acc[p][m];
}

// ---------------- K4: z2p[chunk,b,w] over 2 s; fuses split-reduce + silu of z1 ----
__global__ __launch_bounds__(256) void k4_contract()
{
    __shared__ float zt[40 * 64];    // [(sl*20+c)][b]  (silu'd z1)
    __shared__ float ft[40 * 128];   // [(sl*20+c)][w]
    int chunk = blockIdx.x;
    int tid = threadIdx.x;
    int zbase = chunk * 2560;        // (2*chunk*20)*64

    for (int i = tid; i < 40 * 64; i += 256) {
        float a = g_z1p[0 * ZPSZ + zbase + i] + g_z1p[1 * ZPSZ + zbase + i]
                + g_z1p[2 * ZPSZ + zbase + i] + g_z1p[3 * ZPSZ + zbase + i];
        zt[i] = silu_f(a * (1.0f / (float)NPTS));
    }
    for (int i = tid; i < 40 * 128; i += 256) ft[i] = g_filt2[chunk * 2 * 2560 + i];
    __syncthreads();

    int wq = tid & 15;   // w = wq + 16*k
    int bq = tid >> 4;   // b = bq + 16*i
    float acc[4][8];
#pragma unroll
    for (int i = 0; i < 4; i++)
#pragma unroll
        for (int k = 0; k < 8; k++) acc[i][k] = 0.0f;

    for (int sc = 0; sc < 40; sc++) {
        float z[4];
#pragma unroll
        for (int i = 0; i < 4; i++) z[i] = zt[sc * 64 + bq + 16 * i];
#pragma unroll
        for (int k = 0; k < 8; k++) {
            float f = ft[sc * 128 + wq + 16 * k];
#pragma unroll
            for (int i = 0; i < 4; i++) acc[i][k] += z[i] * f;
        }
    }
#pragma unroll
    for (int i = 0; i < 4; i++)
#pragma unroll
        for (int k = 0; k < 8; k++)
            g_z2p[chunk * (B_ * W_) + (bq + 16 * i) * W_ + wq + 16 * k] = acc[i][k];
}

// ---------------- K5: reduce partials, residual MLP, pool -------------------------
__global__ __launch_bounds__(128) void k5_head(const float* __restrict__ fc1_w,
                                               const float* __restrict__ fc1_b,
                                               const float* __restrict__ fc2_w,
                                               const float* __restrict__ fc2_b,
                                               const float* __restrict__ pool_w,
                                               const float* __restrict__ pool_b,
                                               float* __restrict__ out)
{
    __shared__ float zs[128], r1[128], r2[128];
    int b = blockIdx.x, w = threadIdx.x;

    float a = 0.0f;
#pragma unroll 8
    for (int p = 0; p < K4BLKS; p++) a += g_z2p[p * (B_ * W_) + b * W_ + w];
    a *= (1.0f / (float)S_);
    zs[w] = a;
    __syncthreads();

    float u = fc1_b[w];
#pragma unroll 8
    for (int k = 0; k < 128; k++) u += zs[k] * fc1_w[k * W_ + w];
    r1[w] = silu_f(u) + zs[w];
    __syncthreads();

    u = fc2_b[w];
#pragma unroll 8
    for (int k = 0; k < 128; k++) u += r1[k] * fc2_w[k * W_ + w];
    r2[w] = silu_f(u) + r1[w];
    __syncthreads();

    if (w < 10) {
        float o = pool_b[w];
        for (int k = 0; k < 128; k++) o += r2[k] * pool_w[k * 10 + w];
        out[b * 10 + w] = o;
    }
}

// ---------------- host launcher ---------------------------------------------------
extern "C" void kernel_launch(void* const* d_in, const int* in_sizes, int n_in,
                              void* d_out, int out_size)
{
    const float* data   = (const float*)d_in[0];
    const float* v0     = (const float*)d_in[1];
    const float* v_last = (const float*)d_in[2];
    const float* fl_w1  = (const float*)d_in[3];
    const float* fl_b1  = (const float*)d_in[4];
    const float* fl_w2  = (const float*)d_in[5];
    const float* fl_b2  = (const float*)d_in[6];
    const float* fl_w3  = (const float*)d_in[7];
    const float* fl_b3  = (const float*)d_in[8];
    const float* s_w1   = (const float*)d_in[9];
    const float* s_b1   = (const float*)d_in[10];
    const float* s_w2   = (const float*)d_in[11];
    const float* s_b2   = (const float*)d_in[12];
    const float* fc1_w  = (const float*)d_in[13];
    const float* fc1_b  = (const float*)d_in[14];
    const float* fc2_w  = (const float*)d_in[15];
    const float* fc2_b  = (const float*)d_in[16];
    const float* pool_w = (const float*)d_in[17];
    const float* pool_b = (const float*)d_in[18];

    k1_filt1<<<dim3(7, S_), 128>>>(v_last, fl_w1, fl_b1, fl_w2, fl_b2, fl_w3, fl_b3);
    k2_z1<<<dim3(80, KSPLIT), 128>>>(data);
    k3a_h2<<<S_, 128>>>(v0, s_w1, s_b1);
    k3b_filt2<<<dim3(32, 20), 128>>>(s_w2, s_b2);
    k4_contract<<<K4BLKS, 256>>>();
    k5_head<<<B_, 128>>>(fc1_w, fc1_b, fc2_w, fc2_b, pool_w, pool_b, (float*)d_out);
}

// round 4
// speedup vs baseline: 1.9165x; 1.1381x over previous
#include <cuda_runtime.h>
#include <math.h>

#define B_     64
#define NSIDE  40
#define NPTS   1600
#define S_     512
#define C1_    20
#define W_     128
#define SCN    10240                 // S_*C1_
#define KSPLIT 8                     // k2 n-dim split (200 each)
#define ZPSZ   (SCN * B_)            // one split's z1 partial plane
#define GSPLIT 16                    // kG s-splits (32 s each)
#define GN     (129 * 1280)          // one G partial plane (k x (c*64+b))
#define ZSPLIT 43                    // kZ kc-splits (60 each; 43*60=2580=129*20)

typedef unsigned long long u64;

// ---------------- scratch (device globals; no runtime allocation) ----------------
__device__ __align__(16) float g_filt1[S_ * C1_ * NPTS];   // [sc][n]
__device__ __align__(16) float g_z1p [KSPLIT * ZPSZ];      // [split][sc*64+b]
__device__ __align__(16) float g_h2  [S_ * W_];            // [s][128]
__device__ __align__(16) float g_Gp  [GSPLIT * GN];        // [split][k*1280 + c*64 + b]
__device__ __align__(16) float g_z2p [ZSPLIT * B_ * W_];   // [split][b][w]

// ---------------- f32x2 helpers (Blackwell packed fp32 FMA) -----------------------
__device__ __forceinline__ u64 pk2(float lo, float hi) {
    u64 r; asm("mov.b64 %0, {%1, %2};" : "=l"(r) : "f"(lo), "f"(hi)); return r;
}
__device__ __forceinline__ void upk2(u64 v, float& lo, float& hi) {
    asm("mov.b64 {%0, %1}, %2;" : "=f"(lo), "=f"(hi) : "l"(v));
}
__device__ __forceinline__ void fma2p(u64& d, u64 a, u64 b) {
    asm("fma.rn.f32x2 %0, %1, %2, %0;" : "+l"(d) : "l"(a), "l"(b));
}

__device__ __forceinline__ float silu_f(float x) { return x / (1.0f + __expf(-x)); }
__device__ __forceinline__ float silu_t(float x) {
    float t; asm("tanh.approx.f32 %0, %1;" : "=f"(t) : "f"(0.5f * x));
    return 0.5f * x * (1.0f + t);
}

// ---------------- K1: filt1[sc][n] = MLP(embed(projective coords)) ----------------
#define BP 264   // buf row stride [feat][point]

__device__ __forceinline__ void k1_layer(const float* in, float* out,
                                         const float* w, const float* bias,
                                         int og, int pl)
{
    int ob = og * 10;
    u64 acc[4][5];
#pragma unroll
    for (int ip = 0; ip < 4; ip++)
#pragma unroll
        for (int j = 0; j < 5; j++) acc[ip][j] = pk2(bias[ob + 2*j], bias[ob + 2*j + 1]);
#pragma unroll 4
    for (int i = 0; i < 20; i++) {
        u64 wv[5];
#pragma unroll
        for (int j = 0; j < 5; j++)
            wv[j] = *(const u64*)&w[i * 20 + ob + 2 * j];
#pragma unroll
        for (int ip = 0; ip < 4; ip++) {
            float e = in[i * BP + pl + 64 * ip];
            u64 ed = pk2(e, e);
#pragma unroll
            for (int j = 0; j < 5; j++) fma2p(acc[ip][j], ed, wv[j]);
        }
    }
#pragma unroll
    for (int ip = 0; ip < 4; ip++)
#pragma unroll
        for (int j = 0; j < 5; j++) {
            float a0, a1; upk2(acc[ip][j], a0, a1);
            out[(ob + 2*j)     * BP + pl + 64 * ip] = silu_t(a0);
            out[(ob + 2*j + 1) * BP + pl + 64 * ip] = silu_t(a1);
        }
}

__global__ __launch_bounds__(128) void k1_filt1(
    const float* __restrict__ v_last,
    const float* __restrict__ fw1, const float* __restrict__ fb1,
    const float* __restrict__ fw2, const float* __restrict__ fb2,
    const float* __restrict__ fw3, const float* __restrict__ fb3)
{
    __shared__ __align__(16) float sw1[400], sw2[400], sw3[400];
    __shared__ float sb1[20], sb2[20], sb3[20];
    __shared__ __align__(16) float bufA[20 * BP], bufB[20 * BP];

    int s   = blockIdx.y;
    int n0  = blockIdx.x * 256;
    int tid = threadIdx.x;

    for (int i = tid; i < 400; i += 128) { sw1[i] = fw1[i]; sw2[i] = fw2[i]; sw3[i] = fw3[i]; }
    if (tid < 20) { sb1[tid] = fb1[tid]; sb2[tid] = fb2[tid]; sb3[tid] = fb3[tid]; }

    float v[8];
#pragma unroll
    for (int i = 0; i < 8; i++) v[i] = 0.1f * __ldg(&v_last[s * 8 + i]);

#pragma unroll
    for (int q = 0; q < 2; q++) {
        int p = tid + q * 128;
        int n = n0 + p;
        int ic = n / NSIDE, jc = n - ic * NSIDE;
        float x = -1.0f + (2.0f / 39.0f) * (float)ic;
        float y = -1.0f + (2.0f / 39.0f) * (float)jc;
        float y0 = (1.0f + v[0]) * x + v[1] * y + v[2];
        float y1 = v[3] * x + (1.0f + v[4]) * y + v[5];
        float y2 = v[6] * x + v[7] * y + 1.0f;
        float inv = __frcp_rn(y2);
        float t0 = y0 * inv, t1 = y1 * inv;

        float sa, ca; __sincosf(t0, &sa, &ca);
        bufA[0 * BP + p] = sa; bufA[5 * BP + p] = ca;
#pragma unroll
        for (int k = 1; k < 5; k++) {
            float s2 = 2.0f * sa * ca;
            float c2 = 2.0f * ca * ca - 1.0f;
            bufA[k * BP + p] = s2; bufA[(5 + k) * BP + p] = c2;
            sa = s2; ca = c2;
        }
        __sincosf(t1, &sa, &ca);
        bufA[10 * BP + p] = sa; bufA[15 * BP + p] = ca;
#pragma unroll
        for (int k = 1; k < 5; k++) {
            float s2 = 2.0f * sa * ca;
            float c2 = 2.0f * ca * ca - 1.0f;
            bufA[(10 + k) * BP + p] = s2; bufA[(15 + k) * BP + p] = c2;
            sa = s2; ca = c2;
        }
    }
    __syncthreads();

    int og = tid >> 6;
    int pl = tid & 63;

    k1_layer(bufA, bufB, sw1, sb1, og, pl);
    __syncthreads();
    k1_layer(bufB, bufA, sw2, sb2, og, pl);
    __syncthreads();

    {
        int ob = og * 10;
        u64 acc[4][5];
#pragma unroll
        for (int ip = 0; ip < 4; ip++)
#pragma unroll
            for (int j = 0; j < 5; j++) acc[ip][j] = pk2(sb3[ob + 2*j], sb3[ob + 2*j + 1]);
#pragma unroll 4
        for (int i = 0; i < 20; i++) {
            u64 wv[5];
#pragma unroll
            for (int j = 0; j < 5; j++) wv[j] = *(const u64*)&sw3[i * 20 + ob + 2 * j];
#pragma unroll
            for (int ip = 0; ip < 4; ip++) {
                float e = bufA[i * BP + pl + 64 * ip];
                u64 ed = pk2(e, e);
#pragma unroll
                for (int j = 0; j < 5; j++) fma2p(acc[ip][j], ed, wv[j]);
            }
        }
#pragma unroll
        for (int ip = 0; ip < 4; ip++) {
            int n = n0 + pl + 64 * ip;
            if (n < NPTS) {
#pragma unroll
                for (int j = 0; j < 5; j++) {
                    float a0, a1; upk2(acc[ip][j], a0, a1);
                    g_filt1[(s * C1_ + ob + 2*j)     * NPTS + n] = a0;
                    g_filt1[(s * C1_ + ob + 2*j + 1) * NPTS + n] = a1;
                }
            }
        }
    }
}

// ---------------- K2: z1p[split][sc*64+b] = filt1 . data over 200-wide n-range ----
__global__ __launch_bounds__(128) void k2_z1(const float* __restrict__ data)
{
    __shared__ __align__(16) float dt[40 * 66];    // [k][b]
    __shared__ float ft[40 * 129];                 // [k][sc_local]

    int sc0   = blockIdx.x * 128;
    int split = blockIdx.y;
    int tid   = threadIdx.x;
    int tc    = tid & 7;     // b-pair base 2*tc (+16*jp)
    int sr    = tid >> 3;    // sc local = sr + 16*iq

    u64 acc[8][4];
#pragma unroll
    for (int iq = 0; iq < 8; iq++)
#pragma unroll
        for (int jp = 0; jp < 4; jp++) acc[iq][jp] = 0ull;

    for (int ch = 0; ch < 5; ch++) {
        int base = split * 200 + ch * 40;
        __syncthreads();
        for (int i = tid; i < 64 * 40; i += 128) {
            int b = i / 40, k = i - b * 40;
            dt[k * 66 + b] = data[b * NPTS + base + k];
        }
        for (int i = tid; i < 128 * 40; i += 128) {
            int r = i / 40, k = i - r * 40;
            ft[k * 129 + r] = g_filt1[(sc0 + r) * NPTS + base + k];
        }
        __syncthreads();

#pragma unroll 2
        for (int k = 0; k < 40; k++) {
            u64 fd[8];
#pragma unroll
            for (int iq = 0; iq < 8; iq++) {
                float f = ft[k * 129 + sr + 16 * iq];
                fd[iq] = pk2(f, f);
            }
            u64 dd[4];
#pragma unroll
            for (int jp = 0; jp < 4; jp++)
                dd[jp] = *(const u64*)&dt[k * 66 + 2 * tc + 16 * jp];
#pragma unroll
            for (int iq = 0; iq < 8; iq++)
#pragma unroll
                for (int jp = 0; jp < 4; jp++) fma2p(acc[iq][jp], fd[iq], dd[jp]);
        }
    }

#pragma unroll
    for (int iq = 0; iq < 8; iq++)
#pragma unroll
        for (int jp = 0; jp < 4; jp++)
            *(u64*)&g_z1p[split * ZPSZ + (sc0 + sr + 16 * iq) * B_ + 2 * tc + 16 * jp]
                = acc[iq][jp];
}

// ---------------- K3a: h2[s,:] = silu(embed(v0[s]) @ s_w1 + s_b1) -----------------
__global__ __launch_bounds__(128) void k3a_h2(const float* __restrict__ v0,
                                              const float* __restrict__ s_w1,
                                              const float* __restrict__ s_b1)
{
    __shared__ float e[80];
    int s = blockIdx.x, tid = threadIdx.x;
    if (tid < 80) {
        int d = tid / 10, kk = tid % 10;
        float v = v0[s * 8 + d];
        float f = (float)(1 << (kk % 5));
        e[tid] = (kk < 5) ? __sinf(v * f) : __cosf(v * f);
    }
    __syncthreads();
    float a = s_b1[tid];
#pragma unroll 8
    for (int k = 0; k < 80; k++) a += e[k] * s_w1[k * W_ + tid];
    g_h2[s * W_ + tid] = silu_f(a);
}

// ---------------- KG: G[k,cb] partials = sum over 32 s of h2e[s,k] * z1[s,cb] -----
// grid (16 cb-blocks x 16 s-splits), 256 threads. z1 = silu(reduce(z1p)/N) on load.
// h2e has an appended ones-column (k=128) that makes G[128,:] carry the bias sums.
__global__ __launch_bounds__(256) void kG_contract()
{
    __shared__ float h2s[32 * 129];   // [sl][k], k<128 from g_h2, k==128 -> 1
    __shared__ float z1s[32 * 81];    // [sl][cbl]
    int cb0 = blockIdx.x * 80;
    int sp  = blockIdx.y;
    int s0  = sp * 32;
    int tid = threadIdx.x;

    for (int i = tid; i < 32 * 129; i += 256) {
        int r = i / 129, k = i - r * 129;
        h2s[i] = (k < 128) ? g_h2[(s0 + r) * W_ + k] : 1.0f;
    }
    for (int i = tid; i < 32 * 80; i += 256) {
        int r = i / 80, cb = i - r * 80;
        int idx = (s0 + r) * 1280 + cb0 + cb;
        float a = 0.0f;
#pragma unroll
        for (int p = 0; p < KSPLIT; p++) a += g_z1p[p * ZPSZ + idx];
        z1s[r * 81 + cb] = silu_f(a * (1.0f / (float)NPTS));
    }
    __syncthreads();

    int kq  = tid & 15;   // k = kq + 16*j (j<8), plus k=128 when kq==0 (j==8)
    int cbq = tid >> 4;   // cb = cbq + 16*i (i<5)

    float acc[9][5];
#pragma unroll
    for (int j = 0; j < 9; j++)
#pragma unroll
        for (int i = 0; i < 5; i++) acc[j][i] = 0.0f;

    for (int sl = 0; sl < 32; sl++) {
        float h[9];
#pragma unroll
        for (int j = 0; j < 8; j++) h[j] = h2s[sl * 129 + kq + 16 * j];
        h[8] = h2s[sl * 129 + 128];   // ones column (used only by kq==0)
        float z[5];
#pragma unroll
        for (int i = 0; i < 5; i++) z[i] = z1s[sl * 81 + cbq + 16 * i];
#pragma unroll
        for (int j = 0; j < 9; j++)
#pragma unroll
            for (int i = 0; i < 5; i++) acc[j][i] += h[j] * z[i];
    }

#pragma unroll
    for (int j = 0; j < 9; j++) {
        int k = kq + 16 * j;
        if (j < 8 || kq == 0) {
#pragma unroll
            for (int i = 0; i < 5; i++)
                g_Gp[sp * GN + k * 1280 + cb0 + cbq + 16 * i] = acc[j][i];
        }
    }
}

// ---------------- KZ: z2p[split][b][w] = sum over 60 kc of G[k,cb] * W2ext --------
// grid 43 blocks (60 kc each; 43*60 = 2580 = 129*20), 256 threads, 4b x 8w / thread
__global__ __launch_bounds__(256) void kZ_out(const float* __restrict__ s_w2,
                                              const float* __restrict__ s_b2)
{
    __shared__ float Gt[60 * 64];    // [kcl][b]
    __shared__ float Wt[60 * 128];   // [kcl][w]
    int kc0 = blockIdx.x * 60;
    int tid = threadIdx.x;

    for (int i = tid; i < 60 * 128; i += 256) {
        int kcl = i >> 7, w = i & 127;
        int kc = kc0 + kcl, k = kc / 20, c = kc - k * 20;
        Wt[i] = (k < 128) ? s_w2[k * 2560 + c * 128 + w] : s_b2[c * 128 + w];
    }
    for (int i = tid; i < 60 * 64; i += 256) {
        int kcl = i >> 6, b = i & 63;
        int kc = kc0 + kcl, k = kc / 20, c = kc - k * 20;
        int gi = k * 1280 + c * 64 + b;
        float a = 0.0f;
#pragma unroll
        for (int p = 0; p < GSPLIT; p++) a += g_Gp[p * GN + gi];
        Gt[i] = a;
    }
    __syncthreads();

    int wq = tid & 15;   // w = wq + 16*m
    int bq = tid >> 4;   // b = bq + 16*i  (bq 0..15, i<4)
    float acc[4][8];
#pragma unroll
    for (int i = 0; i < 4; i++)
#pragma unroll
        for (int m = 0; m < 8; m++) acc[i][m] = 0.0f;

    for (int kcl = 0; kcl < 60; kcl++) {
        float g[4];
#pragma unroll
        for (int i = 0; i < 4; i++) g[i] = Gt[kcl * 64 + bq + 16 * i];
#pragma unroll
        for (int m = 0; m < 8; m++) {
            float w = Wt[kcl * 128 + wq + 16 * m];
#pragma unroll
            for (int i = 0; i < 4; i++) acc[i][m] += g[i] * w;
        }
    }
#pragma unroll
    for (int i = 0; i < 4; i++)
#pragma unroll
        for (int m = 0; m < 8; m++)
            g_z2p[blockIdx.x * (B_ * W_) + (bq + 16 * i) * W_ + wq + 16 * m] = acc[i][m];
}

// ---------------- K5: reduce partials, residual MLP, pool -------------------------
__global__ __launch_bounds__(128) void k5_head(const float* __restrict__ fc1_w,
                                               const float* __restrict__ fc1_b,
                                               const float* __restrict__ fc2_w,
                                               const float* __restrict__ fc2_b,
                                               const float* __restrict__ pool_w,
                                               const float* __restrict__ pool_b,
                                               float* __restrict__ out)
{
    __shared__ float zs[128], r1[128], r2[128];
    int b = blockIdx.x, w = threadIdx.x;

    float a = 0.0f;
#pragma unroll
    for (int p = 0; p < ZSPLIT; p++) a += g_z2p[p * (B_ * W_) + b * W_ + w];
    a *= (1.0f / (float)S_);
    zs[w] = a;
    __syncthreads();

    float u = fc1_b[w];
#pragma unroll 8
    for (int k = 0; k < 128; k++) u += zs[k] * fc1_w[k * W_ + w];
    r1[w] = silu_f(u) + zs[w];
    __syncthreads();

    u = fc2_b[w];
#pragma unroll 8
    for (int k = 0; k < 128; k++) u += r1[k] * fc2_w[k * W_ + w];
    r2[w] = silu_f(u) + r1[w];
    __syncthreads();

    if (w < 10) {
        float o = pool_b[w];
        for (int k = 0; k < 128; k++) o += r2[k] * pool_w[k * 10 + w];
        out[b * 10 + w] = o;
    }
}

// ---------------- host launcher ---------------------------------------------------
extern "C" void kernel_launch(void* const* d_in, const int* in_sizes, int n_in,
                              void* d_out, int out_size)
{
    const float* data   = (const float*)d_in[0];
    const float* v0     = (const float*)d_in[1];
    const float* v_last = (const float*)d_in[2];
    const float* fl_w1  = (const float*)d_in[3];
    const float* fl_b1  = (const float*)d_in[4];
    const float* fl_w2  = (const float*)d_in[5];
    const float* fl_b2  = (const float*)d_in[6];
    const float* fl_w3  = (const float*)d_in[7];
    const float* fl_b3  = (const float*)d_in[8];
    const float* s_w1   = (const float*)d_in[9];
    const float* s_b1   = (const float*)d_in[10];
    const float* s_w2   = (const float*)d_in[11];
    const float* s_b2   = (const float*)d_in[12];
    const float* fc1_w  = (const float*)d_in[13];
    const float* fc1_b  = (const float*)d_in[14];
    const float* fc2_w  = (const float*)d_in[15];
    const float* fc2_b  = (const float*)d_in[16];
    const float* pool_w = (const float*)d_in[17];
    const float* pool_b = (const float*)d_in[18];

    k1_filt1<<<dim3(7, S_), 128>>>(v_last, fl_w1, fl_b1, fl_w2, fl_b2, fl_w3, fl_b3);
    k2_z1<<<dim3(80, KSPLIT), 128>>>(data);
    k3a_h2<<<S_, 128>>>(v0, s_w1, s_b1);
    kG_contract<<<dim3(16, GSPLIT), 256>>>();
    kZ_out<<<ZSPLIT, 256>>>(s_w2, s_b2);
    k5_head<<<B_, 128>>>(fc1_w, fc1_b, fc2_w, fc2_b, pool_w, pool_b, (float*)d_out);
}